// round 17
// baseline (speedup 1.0000x reference)
#include <cuda_runtime.h>

#define X 256
#define Y 256
#define Z 192
#define YX (X*Y)
#define NB 2
#define TX 64           // output tile width
#define TY 32           // output tile height
#define CW 34           // float2 cells per row = (TX+4)/2
#define CH 36           // rows = TY+4 (divisible by 3)
#define TCX 17          // thread cols: each owns 2 adjacent cells
#define TCY 12          // thread rows: each owns 3 adjacent rows
#define NTH (TCX*TCY)   // 204 threads
#define ZCHUNKS 4
#define ZCK (Z/ZCHUNKS) /* 48 */

__device__ __forceinline__ float min3(float a, float b, float c) { return fminf(a, fminf(b, c)); }
__device__ __forceinline__ float max3(float a, float b, float c) { return fmaxf(a, fmaxf(b, c)); }
__device__ __forceinline__ float2 fmin3_2(float2 a, float2 b, float2 c) {
    return make_float2(min3(a.x,b.x,c.x), min3(a.y,b.y,c.y));
}
__device__ __forceinline__ float2 fmax3_2(float2 a, float2 b, float2 c) {
    return make_float2(max3(a.x,b.x,c.x), max3(a.y,b.y,c.y));
}

// out = relu(img - dilate3x3x3(erode3x3x3(img))), stride 1, pad 1.
// erode = min-pool (pad +inf), dilate = max-pool (pad -inf via domain mask).
// Thread owns a 2-cell x 3-row patch (12 voxels): the inner x-window boundary
// and the middle row's y-window are in-register. y-exchanges store only edge
// rows r0/r2; x-exchanges read 1 left + 1 right cell per row. 3.33 uniform
// LDS.64 smem ops and 0.33 barrier participations per output voxel
// (champion: 4.0 / 0.5). 204 threads, occupancy 2 -> 160-reg budget fits the
// ~140-reg body. Peeled fill/steady z-march; 256 blocks = one 2/SM wave.
__global__ __launch_bounds__(NTH, 2)
void soft_skel_kernel(const float* __restrict__ img, float* __restrict__ out) {
    __shared__ float2 sA[CH * CW];
    __shared__ float2 sB[CH * CW];

    const int tid = threadIdx.x;
    const int tc  = tid % TCX;           // owns cells 2tc, 2tc+1
    const int tr  = tid / TCX;           // owns rows 3tr .. 3tr+2
    const int bx0 = blockIdx.x * TX;
    const int by0 = blockIdx.y * TY;
    const int bz  = blockIdx.z;
    const int b   = bz / ZCHUNKS;
    const int z0  = (bz % ZCHUNKS) * ZCK;

    const int c0  = 2*tc;                // first owned cell
    const int r0  = 3*tr;                // first owned row
    const int gx0 = bx0 + 2*c0 - 2;      // x of cell c0 (even)
    const int gy0 = by0 + r0 - 2;

    const bool inx0 = (gx0     >= 0) && (gx0     < X);  // cells uniform in x
    const bool inx1 = (gx0 + 2 >= 0) && (gx0 + 2 < X);
    const bool iny0 = (gy0     >= 0) && (gy0     < Y);
    const bool iny1 = (gy0 + 1 >= 0) && (gy0 + 1 < Y);
    const bool iny2 = (gy0 + 2 >= 0) && (gy0 + 2 < Y);

    // output: rows 2..33, cells 1..32
    const bool oC0 = (tc >= 1);                 // cell 2tc
    const bool oC1 = (tc <= TCX - 2);           // cell 2tc+1
    const bool oRw0 = (r0     >= 2) && (r0     <= 33);
    const bool oRw1 = (r0 + 1 >= 2) && (r0 + 1 <= 33);
    const bool oRw2 = (r0 + 2 >= 2) && (r0 + 2 <= 33);

    // smem offsets (float2 units); clamps leave garbage only in shell lanes
    const int xl = (tc == 0)       ? 0      : c0 - 1;   // left thread's c1
    const int xr = (tc == TCX - 1) ? CW - 1 : c0 + 2;   // right thread's c0
    const int yu = (tr == 0)       ? 0      : r0 - 1;   // prev thread's r2
    const int yd = (tr == TCY - 1) ? CH - 1 : r0 + 3;   // next thread's r0
    const int o0 = (r0    ) * CW + c0;   // +1 for cell c1
    const int o1 = (r0 + 1) * CW + c0;
    const int o2 = (r0 + 2) * CW + c0;
    const int oU = yu * CW + c0;
    const int oD = yd * CW + c0;
    const int oL0 = (r0    ) * CW + xl, oX0 = (r0    ) * CW + xr;
    const int oL1 = (r0 + 1) * CW + xl, oX1 = (r0 + 1) * CW + xr;
    const int oL2 = (r0 + 2) * CW + xl, oX2 = (r0 + 2) * CW + xr;

    const float  PINF = __int_as_float(0x7f800000);
    const float  NINF = __int_as_float(0xff800000);
    const float2 PI2  = make_float2(PINF, PINF);
    const float2 NI2  = make_float2(NINF, NINF);

    const long base = (long)b * Z * YX + (long)gy0 * X + gx0;
    const float* pIn = img + base;       // + z*YX
    float*       pO  = out + base + (long)z0 * YX;

    // rings: p = img planes (zi-2, zi-1, zi); q = erode (zi-3, zi-2)
    float2 p0[3][2], p1[3][2], p2[3][2];
    float2 q0[3][2], q1[3][2];
    #pragma unroll
    for (int r = 0; r < 3; ++r)
        #pragma unroll
        for (int c = 0; c < 2; ++c) { q0[r][c] = NI2; q1[r][c] = NI2; }

    #define LOADP(dst, zz) do {                                                 \
        const int _z = (zz);                                                    \
        const bool _zk = (unsigned)_z < (unsigned)Z;                            \
        const long _o = (long)_z * YX;                                          \
        dst[0][0] = (_zk && iny0 && inx0) ? *(const float2*)(pIn + _o)           : PI2; \
        dst[0][1] = (_zk && iny0 && inx1) ? *(const float2*)(pIn + _o + 2)       : PI2; \
        dst[1][0] = (_zk && iny1 && inx0) ? *(const float2*)(pIn + _o + X)       : PI2; \
        dst[1][1] = (_zk && iny1 && inx1) ? *(const float2*)(pIn + _o + X + 2)   : PI2; \
        dst[2][0] = (_zk && iny2 && inx0) ? *(const float2*)(pIn + _o + 2*X)     : PI2; \
        dst[2][1] = (_zk && iny2 && inx1) ? *(const float2*)(pIn + _o + 2*X + 2) : PI2; \
    } while (0)

    // one plane of pipeline work at index zi (erode zc=zi-1, output zo=zi-2)
    #define PLANE_BODY(zi_, EMIT) do {                                          \
        float2 pn[3][2];                                                        \
        LOADP(pn, (zi_) + 1);                                                   \
        float2 zm[3][2];                                                        \
        _Pragma("unroll")                                                       \
        for (int r = 0; r < 3; ++r) {                                           \
            zm[r][0] = fmin3_2(p0[r][0], p1[r][0], p2[r][0]);                   \
            zm[r][1] = fmin3_2(p0[r][1], p1[r][1], p2[r][1]);                   \
        }                                                                       \
        sA[o0]     = zm[0][0];                                                  \
        sA[o0 + 1] = zm[0][1];                                                  \
        sA[o2]     = zm[2][0];                                                  \
        sA[o2 + 1] = zm[2][1];                                                  \
        __syncthreads();                                                        \
        float2 yb[3][2];                                                        \
        {                                                                       \
            float2 U0 = sA[oU], U1 = sA[oU + 1];                                \
            float2 D0 = sA[oD], D1 = sA[oD + 1];                                \
            yb[0][0] = fmin3_2(U0, zm[0][0], zm[1][0]);                         \
            yb[0][1] = fmin3_2(U1, zm[0][1], zm[1][1]);                         \
            yb[1][0] = fmin3_2(zm[0][0], zm[1][0], zm[2][0]);                   \
            yb[1][1] = fmin3_2(zm[0][1], zm[1][1], zm[2][1]);                   \
            yb[2][0] = fmin3_2(zm[1][0], zm[2][0], D0);                         \
            yb[2][1] = fmin3_2(zm[1][1], zm[2][1], D1);                         \
        }                                                                       \
        sB[o0]     = yb[0][0];                                                  \
        sB[o0 + 1] = yb[0][1];                                                  \
        sB[o1]     = yb[1][0];                                                  \
        sB[o1 + 1] = yb[1][1];                                                  \
        sB[o2]     = yb[2][0];                                                  \
        sB[o2 + 1] = yb[2][1];                                                  \
        __syncthreads();                                                        \
        const bool zin = (unsigned)((zi_) - 1) < (unsigned)Z;                   \
        float2 en[3][2];                                                        \
        {                                                                       \
            float2 L[3] = { sB[oL0], sB[oL1], sB[oL2] };                        \
            float2 R[3] = { sB[oX0], sB[oX1], sB[oX2] };                        \
            const bool iy_[3] = { iny0, iny1, iny2 };                           \
            _Pragma("unroll")                                                   \
            for (int r = 0; r < 3; ++r) {                                       \
                const bool m0 = zin && iy_[r] && inx0;                          \
                const bool m1 = zin && iy_[r] && inx1;                          \
                en[r][0].x = m0 ? min3(L[r].y,     yb[r][0].x, yb[r][0].y) : NINF; \
                en[r][0].y = m0 ? min3(yb[r][0].x, yb[r][0].y, yb[r][1].x) : NINF; \
                en[r][1].x = m1 ? min3(yb[r][0].y, yb[r][1].x, yb[r][1].y) : NINF; \
                en[r][1].y = m1 ? min3(yb[r][1].x, yb[r][1].y, R[r].x)     : NINF; \
            }                                                                   \
        }                                                                       \
        float2 dd[3][2];                                                        \
        _Pragma("unroll")                                                       \
        for (int r = 0; r < 3; ++r) {                                           \
            dd[r][0] = fmax3_2(q0[r][0], q1[r][0], en[r][0]);                   \
            dd[r][1] = fmax3_2(q0[r][1], q1[r][1], en[r][1]);                   \
            q0[r][0] = q1[r][0]; q1[r][0] = en[r][0];                           \
            q0[r][1] = q1[r][1]; q1[r][1] = en[r][1];                           \
        }                                                                       \
        sA[o0]     = dd[0][0];                                                  \
        sA[o0 + 1] = dd[0][1];                                                  \
        sA[o2]     = dd[2][0];                                                  \
        sA[o2 + 1] = dd[2][1];                                                  \
        __syncthreads();                                                        \
        float2 m[3][2];                                                         \
        {                                                                       \
            float2 U0 = sA[oU], U1 = sA[oU + 1];                                \
            float2 D0 = sA[oD], D1 = sA[oD + 1];                                \
            m[0][0] = fmax3_2(U0, dd[0][0], dd[1][0]);                          \
            m[0][1] = fmax3_2(U1, dd[0][1], dd[1][1]);                          \
            m[1][0] = fmax3_2(dd[0][0], dd[1][0], dd[2][0]);                    \
            m[1][1] = fmax3_2(dd[0][1], dd[1][1], dd[2][1]);                    \
            m[2][0] = fmax3_2(dd[1][0], dd[2][0], D0);                          \
            m[2][1] = fmax3_2(dd[1][1], dd[2][1], D1);                          \
        }                                                                       \
        sB[o0]     = m[0][0];                                                   \
        sB[o0 + 1] = m[0][1];                                                   \
        sB[o1]     = m[1][0];                                                   \
        sB[o1 + 1] = m[1][1];                                                   \
        sB[o2]     = m[2][0];                                                   \
        sB[o2 + 1] = m[2][1];                                                   \
        __syncthreads();                                                        \
        if (EMIT) {                                                             \
            float2 L[3] = { sB[oL0], sB[oL1], sB[oL2] };                        \
            float2 R[3] = { sB[oX0], sB[oX1], sB[oX2] };                        \
            const bool oRw_[3] = { oRw0, oRw1, oRw2 };                          \
            _Pragma("unroll")                                                   \
            for (int r = 0; r < 3; ++r) {                                       \
                if (oRw_[r]) {                                                  \
                    if (oC0) {                                                  \
                        float2 v;                                               \
                        v.x = fmaxf(p0[r][0].x - max3(L[r].y,     m[r][0].x, m[r][0].y), 0.0f); \
                        v.y = fmaxf(p0[r][0].y - max3(m[r][0].x, m[r][0].y, m[r][1].x), 0.0f); \
                        *(float2*)(pO + r*X) = v;   /* p0 = img at plane zo */  \
                    }                                                           \
                    if (oC1) {                                                  \
                        float2 v;                                               \
                        v.x = fmaxf(p0[r][1].x - max3(m[r][0].y, m[r][1].x, m[r][1].y), 0.0f); \
                        v.y = fmaxf(p0[r][1].y - max3(m[r][1].x, m[r][1].y, R[r].x),    0.0f); \
                        *(float2*)(pO + r*X + 2) = v;                           \
                    }                                                           \
                }                                                               \
            }                                                                   \
            pO += YX;                                                           \
        }                                                                       \
        _Pragma("unroll")                                                       \
        for (int r = 0; r < 3; ++r) {                                           \
            p0[r][0] = p1[r][0]; p1[r][0] = p2[r][0]; p2[r][0] = pn[r][0];      \
            p0[r][1] = p1[r][1]; p1[r][1] = p2[r][1]; p2[r][1] = pn[r][1];      \
        }                                                                       \
    } while (0)

    // ---- direct ring preload: img planes z0-2, z0-1, z0 (no smem, no sync)
    LOADP(p0, z0 - 2);
    LOADP(p1, z0 - 1);
    LOADP(p2, z0);

    // ---- FILL: bodies at zi = z0, z0+1 compute erode z0-1, z0 (no output)
    PLANE_BODY(z0,     false);
    PLANE_BODY(z0 + 1, false);

    // ---- STEADY: zi = z0+2 .. z0+ZCK+1, unconditional output plane zi-2
    #pragma unroll 1
    for (int zi = z0 + 2; zi <= z0 + ZCK + 1; ++zi) {
        PLANE_BODY(zi, true);
    }

    #undef PLANE_BODY
    #undef LOADP
}

extern "C" void kernel_launch(void* const* d_in, const int* in_sizes, int n_in,
                              void* d_out, int out_size) {
    (void)in_sizes; (void)n_in; (void)out_size;
    const float* img = (const float*)d_in[0];
    float* out = (float*)d_out;
    dim3 grid(X / TX, Y / TY, NB * ZCHUNKS);
    soft_skel_kernel<<<grid, NTH>>>(img, out);
}